// round 1
// baseline (speedup 1.0000x reference)
#include <cuda_runtime.h>

// Problem constants
#define H   768
#define NH_ 12
#define HD_ 64
#define B_  16
#define T_  512
#define NROWS (B_ * T_)       // 8192
#define SCALING 2.0f          // lora_alpha / r = 8/4

// -------- device scratch (no allocations allowed) --------
__device__ float g_weff_q[H * H];
__device__ float g_weff_v[H * H];
__device__ float g_q [(size_t)B_ * NH_ * T_ * HD_];
__device__ float g_k [(size_t)B_ * NH_ * T_ * HD_];
__device__ float g_v [(size_t)B_ * NH_ * T_ * HD_];
__device__ float g_ao[(size_t)B_ * NH_ * T_ * HD_];

// ============================================================
// Fold LoRA into effective weight: Weff = W + SCALING * (Bm @ A)
// ============================================================
template <int OUTSEL>   // 1 -> g_weff_q, 2 -> g_weff_v
__global__ void weff_kernel(const float* __restrict__ W,
                            const float* __restrict__ A,
                            const float* __restrict__ Bm) {
    int idx = blockIdx.x * 256 + threadIdx.x;
    if (idx >= H * H) return;
    int j = idx / H, h = idx % H;
    float acc = W[idx];
#pragma unroll
    for (int r = 0; r < 4; r++)
        acc = fmaf(SCALING * Bm[j * 4 + r], A[r * H + h], acc);
    float* out = (OUTSEL == 1) ? g_weff_q : g_weff_v;
    out[idx] = acc;
}

// ============================================================
// Tiled SGEMM: C[n, j] = sum_h A[n,h] * W[j,h] + bias[j]
//   A is [8192, 768] row-major (or gathered from g_ao layout [B,NH,T,HD])
//   W is [768, 768] row-major (x @ W^T semantics)
//   AMODE: 0 = arg pointer row-major, 1 = gather from g_ao
//   WMODE: 0 = arg pointer, 1 = g_weff_q, 2 = g_weff_v
//   CMODE: 0 = arg pointer row-major [N, 768],
//          1/2/3 = scatter to g_q/g_k/g_v as [B, NH, T, HD]
// Tile: 128x128, BK=8, 256 threads, 8x8 per thread.
// ============================================================
template <int AMODE, int WMODE, int CMODE>
__global__ __launch_bounds__(256)
void sgemm_kernel(const float* __restrict__ Aarg,
                  const float* __restrict__ Warg,
                  const float* __restrict__ bias,
                  float* __restrict__ Carg) {
    __shared__ float As[8][132];
    __shared__ float Bs[8][132];

    const float* A = (AMODE == 0) ? Aarg : g_ao;
    const float* W = (WMODE == 0) ? Warg : (WMODE == 1 ? g_weff_q : g_weff_v);

    const int tid = threadIdx.x;
    const int tr  = tid >> 4;          // 0..15
    const int tc  = tid & 15;          // 0..15
    const int rowBase = blockIdx.y * 128;
    const int colBase = blockIdx.x * 128;

    const int lRow = tid >> 1;         // 0..127
    const int lCol = (tid & 1) * 4;    // 0 or 4

    float acc[8][8];
#pragma unroll
    for (int i = 0; i < 8; i++)
#pragma unroll
        for (int j = 0; j < 8; j++) acc[i][j] = 0.f;

    const int aRowG = rowBase + lRow;
    size_t aGatherBase = 0;
    if (AMODE == 1) {
        int b = aRowG >> 9, t = aRowG & 511;
        aGatherBase = (size_t)b * (NH_ * T_ * HD_) + (size_t)t * HD_;
    }

    for (int k0 = 0; k0 < H; k0 += 8) {
        float4 av;
        if (AMODE == 1) {
            int h = k0 + lCol;
            int nh = h >> 6, hd = h & 63;
            av = *reinterpret_cast<const float4*>(
                &A[aGatherBase + (size_t)nh * (T_ * HD_) + hd]);
        } else {
            av = *reinterpret_cast<const float4*>(
                &A[(size_t)aRowG * H + k0 + lCol]);
        }
        As[lCol + 0][lRow] = av.x;
        As[lCol + 1][lRow] = av.y;
        As[lCol + 2][lRow] = av.z;
        As[lCol + 3][lRow] = av.w;

        float4 wv = *reinterpret_cast<const float4*>(
            &W[(size_t)(colBase + lRow) * H + k0 + lCol]);
        Bs[lCol + 0][lRow] = wv.x;
        Bs[lCol + 1][lRow] = wv.y;
        Bs[lCol + 2][lRow] = wv.z;
        Bs[lCol + 3][lRow] = wv.w;

        __syncthreads();

#pragma unroll
        for (int kk = 0; kk < 8; kk++) {
            float ar[8], br[8];
#pragma unroll
            for (int i = 0; i < 8; i++) ar[i] = As[kk][tr * 8 + i];
#pragma unroll
            for (int j = 0; j < 8; j++) br[j] = Bs[kk][tc * 8 + j];
#pragma unroll
            for (int i = 0; i < 8; i++)
#pragma unroll
                for (int j = 0; j < 8; j++)
                    acc[i][j] = fmaf(ar[i], br[j], acc[i][j]);
        }
        __syncthreads();
    }

    float* C = Carg;
    if (CMODE == 1) C = g_q;
    if (CMODE == 2) C = g_k;
    if (CMODE == 3) C = g_v;

#pragma unroll
    for (int j = 0; j < 8; j++) {
        int col = colBase + tc * 8 + j;
        float bj = bias[col];
#pragma unroll
        for (int i = 0; i < 8; i++) {
            int row = rowBase + tr * 8 + i;
            float v = acc[i][j] + bj;
            if (CMODE != 0) {
                int b = row >> 9, t = row & 511;
                int nh = col >> 6, hd = col & 63;
                C[(((size_t)b * NH_ + nh) * T_ + t) * HD_ + hd] = v;
            } else {
                C[(size_t)row * H + col] = v;
            }
        }
    }
}

// ============================================================
// Flash-style attention per (batch, head, q-tile of 64 rows).
// Key mask only (mask==0 -> score=-1e9). Online softmax over
// 16 key tiles of 32. 256 threads: thread = (r = tid>>2, cq = tid&3);
// each thread owns q-row r, score cols {4*jj+cq}, out cols {4*i+cq}.
// Static shared < 48KB.
// ============================================================
#define KT 32
__global__ __launch_bounds__(256)
void attn_kernel(const int* __restrict__ mask) {
    __shared__ __align__(16) float sQ [64][68];
    __shared__ __align__(16) float sKP[KT][68];   // K tile, reused for P
    __shared__ __align__(16) float sV [KT][68];
    __shared__ int sM[KT];

    const int qt = blockIdx.x;                 // 0..7
    const int bh = blockIdx.z * NH_ + blockIdx.y;
    const float* Qp = g_q + (size_t)bh * T_ * HD_ + qt * 64 * HD_;
    const float* Kp = g_k + (size_t)bh * T_ * HD_;
    const float* Vp = g_v + (size_t)bh * T_ * HD_;
    float*       Op = g_ao + (size_t)bh * T_ * HD_ + qt * 64 * HD_;
    const int* mrow = mask + blockIdx.z * T_;

    const int tid = threadIdx.x;
    const int r   = tid >> 2;     // 0..63
    const int cq  = tid & 3;      // 0..3

    // load Q tile (64x64 floats = 1024 float4)
#pragma unroll
    for (int it = 0; it < 4; it++) {
        int e = tid + it * 256;
        int row = e >> 4, c4 = (e & 15) << 2;
        *reinterpret_cast<float4*>(&sQ[row][c4]) =
            *reinterpret_cast<const float4*>(&Qp[row * HD_ + c4]);
    }

    float m_prev = -1e30f, l = 0.f;
    float acc[16];
#pragma unroll
    for (int i = 0; i < 16; i++) acc[i] = 0.f;

    for (int kt = 0; kt < T_ / KT; kt++) {
        __syncthreads();   // prev-iter consumers done before overwrite
        const float* Kt = Kp + kt * KT * HD_;
        const float* Vt = Vp + kt * KT * HD_;
        // KT*64 floats = 512 float4 each
#pragma unroll
        for (int it = 0; it < 2; it++) {
            int e = tid + it * 256;
            int row = e >> 4, c4 = (e & 15) << 2;
            *reinterpret_cast<float4*>(&sKP[row][c4]) =
                *reinterpret_cast<const float4*>(&Kt[row * HD_ + c4]);
            *reinterpret_cast<float4*>(&sV[row][c4]) =
                *reinterpret_cast<const float4*>(&Vt[row * HD_ + c4]);
        }
        if (tid < KT) sM[tid] = mrow[kt * KT + tid];
        __syncthreads();

        // scores for this thread's 8 columns
        float s[KT / 4];
#pragma unroll
        for (int jj = 0; jj < KT / 4; jj++) {
            int j = (jj << 2) + cq;
            float d0 = 0.f;
#pragma unroll
            for (int d = 0; d < HD_; d++)
                d0 = fmaf(sQ[r][d], sKP[j][d], d0);
            s[jj] = sM[j] ? d0 * 0.125f : -1e9f;
        }
        __syncthreads();   // all done reading sKP as K

        // row max across the 4 lanes sharing row r
        float mt = s[0];
#pragma unroll
        for (int jj = 1; jj < KT / 4; jj++) mt = fmaxf(mt, s[jj]);
        mt = fmaxf(mt, __shfl_xor_sync(0xffffffffu, mt, 1));
        mt = fmaxf(mt, __shfl_xor_sync(0xffffffffu, mt, 2));

        float m_new = fmaxf(m_prev, mt);
        float corr  = __expf(m_prev - m_new);
        float psum  = 0.f;
#pragma unroll
        for (int jj = 0; jj < KT / 4; jj++) {
            float p = __expf(s[jj] - m_new);
            psum += p;
            sKP[(jj << 2) + cq][r] = p;   // store P transposed: P[j][r]
        }
        psum += __shfl_xor_sync(0xffffffffu, psum, 1);
        psum += __shfl_xor_sync(0xffffffffu, psum, 2);
        l = l * corr + psum;
        m_prev = m_new;
#pragma unroll
        for (int i = 0; i < 16; i++) acc[i] *= corr;
        __syncthreads();   // P visible to all

        // O[r][d] += sum_j P[j][r] * V[j][d]
#pragma unroll 4
        for (int j = 0; j < KT; j++) {
            float p = sKP[j][r];
#pragma unroll
            for (int i = 0; i < 16; i++)
                acc[i] = fmaf(p, sV[j][(i << 2) + cq], acc[i]);
        }
    }

    float inv = 1.0f / l;
#pragma unroll
    for (int i = 0; i < 16; i++)
        Op[r * HD_ + (i << 2) + cq] = acc[i] * inv;
}

// ============================================================
// launch
// ============================================================
extern "C" void kernel_launch(void* const* d_in, const int* in_sizes, int n_in,
                              void* d_out, int out_size) {
    (void)in_sizes; (void)n_in; (void)out_size;
    const float* x  = (const float*)d_in[0];
    const int*  mask = (const int*) d_in[1];
    const float* Wq = (const float*)d_in[2];
    const float* bq = (const float*)d_in[3];
    const float* Aq = (const float*)d_in[4];
    const float* Bq = (const float*)d_in[5];
    const float* Wk = (const float*)d_in[6];
    const float* bk = (const float*)d_in[7];
    const float* Wv = (const float*)d_in[8];
    const float* bv = (const float*)d_in[9];
    const float* Av = (const float*)d_in[10];
    const float* Bv = (const float*)d_in[11];
    const float* Wo = (const float*)d_in[12];
    const float* bo = (const float*)d_in[13];
    float* out = (float*)d_out;

    // 1) fold LoRA into effective weights
    weff_kernel<1><<<(H * H + 255) / 256, 256>>>(Wq, Aq, Bq);
    weff_kernel<2><<<(H * H + 255) / 256, 256>>>(Wv, Av, Bv);

    // 2) Q/K/V projections (scatter into [B, NH, T, HD])
    dim3 gg(H / 128, NROWS / 128);   // (6, 64)
    sgemm_kernel<0, 1, 1><<<gg, 256>>>(x, nullptr, bq, nullptr);  // Q
    sgemm_kernel<0, 0, 2><<<gg, 256>>>(x, Wk,      bk, nullptr);  // K
    sgemm_kernel<0, 2, 3><<<gg, 256>>>(x, nullptr, bv, nullptr);  // V

    // 3) attention
    attn_kernel<<<dim3(T_ / 64, NH_, B_), 256>>>(mask);

    // 4) output projection (gather from [B, NH, T, HD])
    sgemm_kernel<1, 0, 0><<<gg, 256>>>(nullptr, Wo, bo, out);
}

// round 3
// speedup vs baseline: 1.0583x; 1.0583x over previous
#include <cuda_runtime.h>
#include <cstdint>

// Problem constants
#define H   768
#define NH_ 12
#define HD_ 64
#define B_  16
#define T_  512
#define NROWS (B_ * T_)       // 8192
#define SCALING 2.0f          // lora_alpha / r = 8/4

// -------- device scratch (no allocations allowed) --------
__device__ float g_weff_q[H * H];
__device__ float g_weff_v[H * H];
__device__ float g_q [(size_t)NROWS * H];
__device__ float g_k [(size_t)NROWS * H];
__device__ float g_v [(size_t)NROWS * H];
__device__ float g_ao[(size_t)NROWS * H];

// ============================================================
// helpers
// ============================================================
__device__ __forceinline__ uint32_t f2tf32(float x) {
    uint32_t r;
    asm("cvt.rna.tf32.f32 %0, %1;" : "=r"(r) : "f"(x));
    return r;
}

__device__ __forceinline__ void mma_tf32(float* d, const uint32_t* a, const uint32_t* b) {
    asm volatile(
        "mma.sync.aligned.m16n8k8.row.col.f32.tf32.tf32.f32 "
        "{%0,%1,%2,%3}, {%4,%5,%6,%7}, {%8,%9}, {%0,%1,%2,%3};"
        : "+f"(d[0]), "+f"(d[1]), "+f"(d[2]), "+f"(d[3])
        : "r"(a[0]), "r"(a[1]), "r"(a[2]), "r"(a[3]), "r"(b[0]), "r"(b[1]));
}

// ============================================================
// Fold LoRA into effective weight: Weff = W + SCALING * (Bm @ A)
// ============================================================
template <int OUTSEL>
__global__ void weff_kernel(const float* __restrict__ W,
                            const float* __restrict__ A,
                            const float* __restrict__ Bm) {
    int idx = blockIdx.x * 256 + threadIdx.x;
    if (idx >= H * H) return;
    int j = idx / H, h = idx % H;
    float acc = W[idx];
#pragma unroll
    for (int r = 0; r < 4; r++)
        acc = fmaf(SCALING * Bm[j * 4 + r], A[r * H + h], acc);
    float* out = (OUTSEL == 1) ? g_weff_q : g_weff_v;
    out[idx] = acc;
}

// ============================================================
// tf32 mma.sync GEMM: C[n, j] = sum_h A[n,h] * W[j,h] + bias[j]
// A: [8192, 768] rm, W: [768, 768] rm (x @ W^T), C: [8192, 768] rm.
// Tile 128x128, BK=16, 256 threads = 8 warps; warp computes 64x32
// as 4x4 grid of m16n8k8. SMEM pitch 20 (conflict-free fragments).
// grid = (6, 64).
// ============================================================
#define PITCH 20
#define NITER (H / 16)   // 48

__global__ __launch_bounds__(256)
void gemm_mma(const float* __restrict__ A, const float* __restrict__ W,
              const float* __restrict__ bias, float* __restrict__ C) {
    __shared__ uint32_t As[128 * PITCH];
    __shared__ uint32_t Ws[128 * PITCH];

    const int tid  = threadIdx.x;
    const int wid  = tid >> 5;
    const int lane = tid & 31;
    const int lr   = lane >> 2;   // 0..7
    const int lc   = lane & 3;    // 0..3
    const int rowBase = blockIdx.y * 128;
    const int colBase = blockIdx.x * 128;
    const int mwarp = (wid & 1) * 64;
    const int nwarp = (wid >> 1) * 32;

    // per-thread gmem/smem slots: 2 float4 per operand tile
    const int e0 = tid,        row0 = e0 >> 2, c40 = (e0 & 3) << 2;
    const int e1 = tid + 256,  row1 = e1 >> 2, c41 = (e1 & 3) << 2;
    const float* pA0 = A + (size_t)(rowBase + row0) * H + c40;
    const float* pA1 = A + (size_t)(rowBase + row1) * H + c41;
    const float* pW0 = W + (size_t)(colBase + row0) * H + c40;
    const float* pW1 = W + (size_t)(colBase + row1) * H + c41;
    const int s0 = row0 * PITCH + c40;
    const int s1 = row1 * PITCH + c41;

    float acc[4][4][4];
#pragma unroll
    for (int mt = 0; mt < 4; mt++)
#pragma unroll
        for (int nt = 0; nt < 4; nt++)
#pragma unroll
            for (int i = 0; i < 4; i++) acc[mt][nt][i] = 0.f;

    float4 fa0 = *reinterpret_cast<const float4*>(pA0);
    float4 fa1 = *reinterpret_cast<const float4*>(pA1);
    float4 fw0 = *reinterpret_cast<const float4*>(pW0);
    float4 fw1 = *reinterpret_cast<const float4*>(pW1);

    for (int it = 0; it < NITER; it++) {
        // convert to tf32 (rna) and store to smem
        {
            uint4 u;
            u.x = f2tf32(fa0.x); u.y = f2tf32(fa0.y); u.z = f2tf32(fa0.z); u.w = f2tf32(fa0.w);
            *reinterpret_cast<uint4*>(&As[s0]) = u;
            u.x = f2tf32(fa1.x); u.y = f2tf32(fa1.y); u.z = f2tf32(fa1.z); u.w = f2tf32(fa1.w);
            *reinterpret_cast<uint4*>(&As[s1]) = u;
            u.x = f2tf32(fw0.x); u.y = f2tf32(fw0.y); u.z = f2tf32(fw0.z); u.w = f2tf32(fw0.w);
            *reinterpret_cast<uint4*>(&Ws[s0]) = u;
            u.x = f2tf32(fw1.x); u.y = f2tf32(fw1.y); u.z = f2tf32(fw1.z); u.w = f2tf32(fw1.w);
            *reinterpret_cast<uint4*>(&Ws[s1]) = u;
        }
        __syncthreads();

        if (it + 1 < NITER) {
            const int off = (it + 1) * 16;
            fa0 = *reinterpret_cast<const float4*>(pA0 + off);
            fa1 = *reinterpret_cast<const float4*>(pA1 + off);
            fw0 = *reinterpret_cast<const float4*>(pW0 + off);
            fw1 = *reinterpret_cast<const float4*>(pW1 + off);
        }

#pragma unroll
        for (int ks = 0; ks < 2; ks++) {
            const int kb = ks * 8 + lc;
            uint32_t af[4][4], bf[4][2];
#pragma unroll
            for (int mt = 0; mt < 4; mt++) {
                const int m0 = mwarp + mt * 16 + lr;
                af[mt][0] = As[m0 * PITCH + kb];
                af[mt][1] = As[(m0 + 8) * PITCH + kb];
                af[mt][2] = As[m0 * PITCH + kb + 4];
                af[mt][3] = As[(m0 + 8) * PITCH + kb + 4];
            }
#pragma unroll
            for (int nt = 0; nt < 4; nt++) {
                const int n0 = nwarp + nt * 8 + lr;
                bf[nt][0] = Ws[n0 * PITCH + kb];
                bf[nt][1] = Ws[n0 * PITCH + kb + 4];
            }
#pragma unroll
            for (int mt = 0; mt < 4; mt++)
#pragma unroll
                for (int nt = 0; nt < 4; nt++)
                    mma_tf32(acc[mt][nt], af[mt], bf[nt]);
        }
        __syncthreads();
    }

    // epilogue with bias
#pragma unroll
    for (int mt = 0; mt < 4; mt++) {
        const int r0 = rowBase + mwarp + mt * 16 + lr;
#pragma unroll
        for (int nt = 0; nt < 4; nt++) {
            const int c0 = colBase + nwarp + nt * 8 + lc * 2;
            const float b0 = __ldg(&bias[c0]);
            const float b1 = __ldg(&bias[c0 + 1]);
            float2 v0 = { acc[mt][nt][0] + b0, acc[mt][nt][1] + b1 };
            float2 v1 = { acc[mt][nt][2] + b0, acc[mt][nt][3] + b1 };
            *reinterpret_cast<float2*>(&C[(size_t)r0 * H + c0])       = v0;
            *reinterpret_cast<float2*>(&C[(size_t)(r0 + 8) * H + c0]) = v1;
        }
    }
}

// ============================================================
// Flash-style attention. Buffers row-major [8192, 768];
// head h occupies cols [h*64, h*64+64).
// block = (qtile, head, batch); 256 threads: r = tid>>2, cq = tid&3.
// ============================================================
#define KT 32
__global__ __launch_bounds__(256)
void attn_kernel(const int* __restrict__ mask) {
    __shared__ __align__(16) float sQ [64][68];
    __shared__ __align__(16) float sKP[KT][68];   // K tile, reused for P
    __shared__ __align__(16) float sV [KT][68];
    __shared__ int sM[KT];

    const int qt = blockIdx.x;
    const int nh = blockIdx.y;
    const int b  = blockIdx.z;
    const float* Qp = g_q + ((size_t)(b * T_ + qt * 64)) * H + nh * HD_;
    const float* Kp = g_k + ((size_t)(b * T_)) * H + nh * HD_;
    const float* Vp = g_v + ((size_t)(b * T_)) * H + nh * HD_;
    float*       Op = g_ao + ((size_t)(b * T_ + qt * 64)) * H + nh * HD_;
    const int* mrow = mask + b * T_;

    const int tid = threadIdx.x;
    const int r   = tid >> 2;
    const int cq  = tid & 3;

#pragma unroll
    for (int it = 0; it < 4; it++) {
        int e = tid + it * 256;
        int row = e >> 4, c4 = (e & 15) << 2;
        *reinterpret_cast<float4*>(&sQ[row][c4]) =
            *reinterpret_cast<const float4*>(&Qp[row * H + c4]);
    }

    float m_prev = -1e30f, l = 0.f;
    float acc[16];
#pragma unroll
    for (int i = 0; i < 16; i++) acc[i] = 0.f;

    for (int kt = 0; kt < T_ / KT; kt++) {
        __syncthreads();
        const float* Kt = Kp + kt * KT * H;
        const float* Vt = Vp + kt * KT * H;
#pragma unroll
        for (int it = 0; it < 2; it++) {
            int e = tid + it * 256;
            int row = e >> 4, c4 = (e & 15) << 2;
            *reinterpret_cast<float4*>(&sKP[row][c4]) =
                *reinterpret_cast<const float4*>(&Kt[row * H + c4]);
            *reinterpret_cast<float4*>(&sV[row][c4]) =
                *reinterpret_cast<const float4*>(&Vt[row * H + c4]);
        }
        if (tid < KT) sM[tid] = mrow[kt * KT + tid];
        __syncthreads();

        // scores: d-outer, j-inner (register-accumulated)
        float s[KT / 4];
#pragma unroll
        for (int jj = 0; jj < KT / 4; jj++) s[jj] = 0.f;
#pragma unroll 8
        for (int d = 0; d < HD_; d++) {
            float qd = sQ[r][d];
#pragma unroll
            for (int jj = 0; jj < KT / 4; jj++)
                s[jj] = fmaf(qd, sKP[(jj << 2) + cq][d], s[jj]);
        }
#pragma unroll
        for (int jj = 0; jj < KT / 4; jj++)
            s[jj] = sM[(jj << 2) + cq] ? s[jj] * 0.125f : -1e9f;
        __syncthreads();

        float mt = s[0];
#pragma unroll
        for (int jj = 1; jj < KT / 4; jj++) mt = fmaxf(mt, s[jj]);
        mt = fmaxf(mt, __shfl_xor_sync(0xffffffffu, mt, 1));
        mt = fmaxf(mt, __shfl_xor_sync(0xffffffffu, mt, 2));

        float m_new = fmaxf(m_prev, mt);
        float corr  = __expf(m_prev - m_new);
        float psum  = 0.f;
#pragma unroll
        for (int jj = 0; jj < KT / 4; jj++) {
            float p = __expf(s[jj] - m_new);
            psum += p;
            sKP[(jj << 2) + cq][r] = p;   // P transposed: P[j][r]
        }
        psum += __shfl_xor_sync(0xffffffffu, psum, 1);
        psum += __shfl_xor_sync(0xffffffffu, psum, 2);
        l = l * corr + psum;
        m_prev = m_new;
#pragma unroll
        for (int i = 0; i < 16; i++) acc[i] *= corr;
        __syncthreads();

#pragma unroll 4
        for (int j = 0; j < KT; j++) {
            float p = sKP[j][r];
#pragma unroll
            for (int i = 0; i < 16; i++)
                acc[i] = fmaf(p, sV[j][(i << 2) + cq], acc[i]);
        }
    }

    float inv = 1.0f / l;
#pragma unroll
    for (int i = 0; i < 16; i++)
        Op[r * H + (i << 2) + cq] = acc[i] * inv;
}

// ============================================================
// launch
// ============================================================
extern "C" void kernel_launch(void* const* d_in, const int* in_sizes, int n_in,
                              void* d_out, int out_size) {
    (void)in_sizes; (void)n_in; (void)out_size;
    const float* x  = (const float*)d_in[0];
    const int*  mask = (const int*) d_in[1];
    const float* Wq = (const float*)d_in[2];
    const float* bq = (const float*)d_in[3];
    const float* Aq = (const float*)d_in[4];
    const float* Bq = (const float*)d_in[5];
    const float* Wk = (const float*)d_in[6];
    const float* bk = (const float*)d_in[7];
    const float* Wv = (const float*)d_in[8];
    const float* bv = (const float*)d_in[9];
    const float* Av = (const float*)d_in[10];
    const float* Bv = (const float*)d_in[11];
    const float* Wo = (const float*)d_in[12];
    const float* bo = (const float*)d_in[13];
    float* out = (float*)d_out;

    float *pweff_q, *pweff_v, *pq, *pk, *pv, *pao;
    cudaGetSymbolAddress((void**)&pweff_q, g_weff_q);
    cudaGetSymbolAddress((void**)&pweff_v, g_weff_v);
    cudaGetSymbolAddress((void**)&pq, g_q);
    cudaGetSymbolAddress((void**)&pk, g_k);
    cudaGetSymbolAddress((void**)&pv, g_v);
    cudaGetSymbolAddress((void**)&pao, g_ao);

    // 1) fold LoRA into effective weights
    weff_kernel<1><<<(H * H + 255) / 256, 256>>>(Wq, Aq, Bq);
    weff_kernel<2><<<(H * H + 255) / 256, 256>>>(Wv, Av, Bv);

    // 2) Q/K/V projections (tf32 mma.sync)
    dim3 gg(H / 128, NROWS / 128);   // (6, 64)
    gemm_mma<<<gg, 256>>>(x, pweff_q, bq, pq);
    gemm_mma<<<gg, 256>>>(x, Wk,      bk, pk);
    gemm_mma<<<gg, 256>>>(x, pweff_v, bv, pv);

    // 3) attention
    attn_kernel<<<dim3(T_ / 64, NH_, B_), 256>>>(mask);

    // 4) output projection
    gemm_mma<<<gg, 256>>>(pao, Wo, bo, out);
}

// round 4
// speedup vs baseline: 3.2728x; 3.0923x over previous
#include <cuda_runtime.h>
#include <cstdint>

#define H   768
#define NH_ 12
#define HD_ 64
#define B_  16
#define T_  512
#define NROWS (B_ * T_)
#define SCALING 2.0f

// -------- device scratch --------
__device__ float g_xt  [(size_t)NROWS * H];   // x rounded to tf32
__device__ float g_weff_q[H * H];
__device__ float g_weff_v[H * H];
__device__ float g_wkt [H * H];
__device__ float g_wot [H * H];
__device__ float g_q [(size_t)NROWS * H];
__device__ float g_k [(size_t)NROWS * H];
__device__ float g_v [(size_t)NROWS * H];
__device__ float g_ao[(size_t)NROWS * H];
__device__ int   g_idx[B_ * T_];
__device__ int   g_vcnt[B_];

// ============================================================
// helpers
// ============================================================
__device__ __forceinline__ float rna_tf32(float x) {
    uint32_t u;
    asm("cvt.rna.tf32.f32 %0, %1;" : "=r"(u) : "f"(x));
    return __uint_as_float(u);
}

__device__ __forceinline__ void mma_tf32(float* d, const uint32_t* a, const uint32_t* b) {
    asm volatile(
        "mma.sync.aligned.m16n8k8.row.col.f32.tf32.tf32.f32 "
        "{%0,%1,%2,%3}, {%4,%5,%6,%7}, {%8,%9}, {%0,%1,%2,%3};"
        : "+f"(d[0]), "+f"(d[1]), "+f"(d[2]), "+f"(d[3])
        : "r"(a[0]), "r"(a[1]), "r"(a[2]), "r"(a[3]), "r"(b[0]), "r"(b[1]));
}

__device__ __forceinline__ uint32_t smem_u32(const void* p) {
    uint32_t a;
    asm("{ .reg .u64 t; cvta.to.shared.u64 t, %1; cvt.u32.u64 %0, t; }"
        : "=r"(a) : "l"(p));
    return a;
}

__device__ __forceinline__ void cp_async16(uint32_t dst, const void* src) {
    asm volatile("cp.async.ca.shared.global [%0], [%1], 16;" :: "r"(dst), "l"(src));
}
#define CP_COMMIT() asm volatile("cp.async.commit_group;" ::: "memory")
#define CP_WAIT(n)  asm volatile("cp.async.wait_group %0;" :: "n"(n) : "memory")

// polynomial 2^t for t <= 0 (FMA pipe, no MUFU). rel err ~1e-5.
__device__ __forceinline__ float exp2p(float t) {
    t = fmaxf(t, -126.f);
    float fi = floorf(t);
    float f  = t - fi;
    float p  = 0.0001540353f;
    p = fmaf(p, f, 0.0013333558f);
    p = fmaf(p, f, 0.0096181291f);
    p = fmaf(p, f, 0.0555041087f);
    p = fmaf(p, f, 0.2402265070f);
    p = fmaf(p, f, 0.6931471806f);
    p = fmaf(p, f, 1.0f);
    int ei = (int)fi;
    return p * __int_as_float((ei + 127) << 23);
}
#define LOG2E 1.4426950408889634f

// ============================================================
// prep kernels
// ============================================================
__global__ void cvt_rna_kernel(const float* __restrict__ in, float* __restrict__ out, int n) {
    int i = blockIdx.x * 256 + threadIdx.x;
    if (i < n) out[i] = rna_tf32(in[i]);
}

template <int OUTSEL>
__global__ void weff_kernel(const float* __restrict__ W,
                            const float* __restrict__ A,
                            const float* __restrict__ Bm) {
    int idx = blockIdx.x * 256 + threadIdx.x;
    if (idx >= H * H) return;
    int j = idx / H, h = idx % H;
    float acc = W[idx];
#pragma unroll
    for (int r = 0; r < 4; r++)
        acc = fmaf(SCALING * Bm[j * 4 + r], A[r * H + h], acc);
    float* out = (OUTSEL == 1) ? g_weff_q : g_weff_v;
    out[idx] = rna_tf32(acc);
}

// per-batch compaction of valid key indices (deterministic, ballot-based)
__global__ void compact_kernel(const int* __restrict__ mask) {
    int b = blockIdx.x;
    int lane = threadIdx.x;
    int base = 0;
    for (int c = 0; c < T_ / 32; c++) {
        int key = c * 32 + lane;
        int v = (mask[b * T_ + key] != 0);
        unsigned bal = __ballot_sync(0xffffffffu, v);
        int pos = base + __popc(bal & ((1u << lane) - 1u));
        if (v) g_idx[b * T_ + pos] = key;
        base += __popc(bal);
    }
    if (lane == 0) g_vcnt[b] = base;
}

// ============================================================
// tf32 GEMM, cp.async double-buffered, operands pre-rounded.
// C[n,j] = sum_h A[n,h]*W[j,h] + bias[j]
// Tile 128x128, BK=16, 256 thr (8 warps, 64x32 each).
// grid.x = 6*nsel (W/bias/C selected by blockIdx.x/6), grid.y = 64.
// ============================================================
#define PITCH 20
#define NITER (H / 16)          // 48
#define STG_FLTS (128 * PITCH)  // 2560

__global__ __launch_bounds__(256)
void gemm_mma(const float* __restrict__ A,
              const float* W0, const float* W1, const float* W2,
              const float* b0, const float* b1, const float* b2,
              float* C0, float* C1, float* C2) {
    __shared__ float sA[2 * STG_FLTS];
    __shared__ float sW[2 * STG_FLTS];

    const int sel = blockIdx.x / 6;
    const float* W    = (sel == 0) ? W0 : (sel == 1) ? W1 : W2;
    const float* bias = (sel == 0) ? b0 : (sel == 1) ? b1 : b2;
    float*       C    = (sel == 0) ? C0 : (sel == 1) ? C1 : C2;

    const int tid  = threadIdx.x;
    const int wid  = tid >> 5;
    const int lane = tid & 31;
    const int lr   = lane >> 2;
    const int lc   = lane & 3;
    const int rowBase = blockIdx.y * 128;
    const int colBase = (blockIdx.x % 6) * 128;
    const int mwarp = (wid & 1) * 64;
    const int nwarp = (wid >> 1) * 32;

    const int e0 = tid,       row0 = e0 >> 2, c40 = (e0 & 3) << 2;
    const int e1 = tid + 256, row1 = e1 >> 2, c41 = (e1 & 3) << 2;
    const float* pA0 = A + (size_t)(rowBase + row0) * H + c40;
    const float* pA1 = A + (size_t)(rowBase + row1) * H + c41;
    const float* pW0 = W + (size_t)(colBase + row0) * H + c40;
    const float* pW1 = W + (size_t)(colBase + row1) * H + c41;
    const int s0 = row0 * PITCH + c40;
    const int s1 = row1 * PITCH + c41;

    const uint32_t aA = smem_u32(sA);
    const uint32_t aW = smem_u32(sW);

    float acc[4][4][4];
#pragma unroll
    for (int mt = 0; mt < 4; mt++)
#pragma unroll
        for (int nt = 0; nt < 4; nt++)
#pragma unroll
            for (int i = 0; i < 4; i++) acc[mt][nt][i] = 0.f;

    // prologue: stage 0
    {
        cp_async16(aA + (uint32_t)(s0) * 4, pA0);
        cp_async16(aA + (uint32_t)(s1) * 4, pA1);
        cp_async16(aW + (uint32_t)(s0) * 4, pW0);
        cp_async16(aW + (uint32_t)(s1) * 4, pW1);
        CP_COMMIT();
    }

    for (int it = 0; it < NITER; it++) {
        if (it + 1 < NITER) {
            const int koff = (it + 1) * 16;
            const uint32_t stoff = (uint32_t)(((it + 1) & 1) * STG_FLTS) * 4;
            cp_async16(aA + stoff + (uint32_t)s0 * 4, pA0 + koff);
            cp_async16(aA + stoff + (uint32_t)s1 * 4, pA1 + koff);
            cp_async16(aW + stoff + (uint32_t)s0 * 4, pW0 + koff);
            cp_async16(aW + stoff + (uint32_t)s1 * 4, pW1 + koff);
            CP_COMMIT();
            CP_WAIT(1);
        } else {
            CP_WAIT(0);
        }
        __syncthreads();

        const float* cAf = sA + (it & 1) * STG_FLTS;
        const float* cWf = sW + (it & 1) * STG_FLTS;
#pragma unroll
        for (int ks = 0; ks < 2; ks++) {
            const int kb = ks * 8 + lc;
            uint32_t af[4][4], bf[4][2];
#pragma unroll
            for (int mt = 0; mt < 4; mt++) {
                const int m0 = mwarp + mt * 16 + lr;
                af[mt][0] = __float_as_uint(cAf[m0 * PITCH + kb]);
                af[mt][1] = __float_as_uint(cAf[(m0 + 8) * PITCH + kb]);
                af[mt][2] = __float_as_uint(cAf[m0 * PITCH + kb + 4]);
                af[mt][3] = __float_as_uint(cAf[(m0 + 8) * PITCH + kb + 4]);
            }
#pragma unroll
            for (int nt = 0; nt < 4; nt++) {
                const int n0 = nwarp + nt * 8 + lr;
                bf[nt][0] = __float_as_uint(cWf[n0 * PITCH + kb]);
                bf[nt][1] = __float_as_uint(cWf[n0 * PITCH + kb + 4]);
            }
#pragma unroll
            for (int mt = 0; mt < 4; mt++)
#pragma unroll
                for (int nt = 0; nt < 4; nt++)
                    mma_tf32(acc[mt][nt], af[mt], bf[nt]);
        }
        __syncthreads();
    }

#pragma unroll
    for (int mt = 0; mt < 4; mt++) {
        const int r0 = rowBase + mwarp + mt * 16 + lr;
#pragma unroll
        for (int nt = 0; nt < 4; nt++) {
            const int c0 = colBase + nwarp + nt * 8 + lc * 2;
            const float bb0 = __ldg(&bias[c0]);
            const float bb1 = __ldg(&bias[c0 + 1]);
            float2 v0 = { acc[mt][nt][0] + bb0, acc[mt][nt][1] + bb1 };
            float2 v1 = { acc[mt][nt][2] + bb0, acc[mt][nt][3] + bb1 };
            *reinterpret_cast<float2*>(&C[(size_t)r0 * H + c0])       = v0;
            *reinterpret_cast<float2*>(&C[(size_t)(r0 + 8) * H + c0]) = v1;
        }
    }
}

// ============================================================
// Attention v2: compacted keys, register-blocked 4x8 tiles,
// polynomial exp2, fp32 math. 128 threads, 64 q-rows per block.
// grid = (8, 12, 16). Output rounded to tf32 for the O-proj GEMM.
// ============================================================
#define AP 66   // smem pitch (floats): conflict-free for stride-row access

extern __shared__ float at_smem[];

__global__ __launch_bounds__(128)
void attn_kernel(const float* __restrict__ Q, const float* __restrict__ K,
                 const float* __restrict__ V, float* __restrict__ O) {
    float* sQ  = at_smem;
    float* sKP = sQ + 64 * AP;       // K tile; reused for P (transposed)
    float* sV  = sKP + 64 * AP;
    int*   sIdx = (int*)(sV + 64 * AP);

    const int qt = blockIdx.x;
    const int nh = blockIdx.y;
    const int b  = blockIdx.z;
    const int tid = threadIdx.x;
    const int ty = tid >> 3;     // 0..15
    const int tx = tid & 7;      // 0..7

    const int vcnt = g_vcnt[b];
    for (int i = tid; i < T_; i += 128) sIdx[i] = g_idx[b * T_ + i];

    const float* Qb = Q + (size_t)(b * T_ + qt * 64) * H + nh * HD_;
    const float* Kb = K + (size_t)(b * T_) * H + nh * HD_;
    const float* Vb = V + (size_t)(b * T_) * H + nh * HD_;

#pragma unroll
    for (int it = 0; it < 16; it++) {
        int e = tid + it * 128;
        int row = e >> 5, c2 = (e & 31) << 1;
        float2 v = *reinterpret_cast<const float2*>(&Qb[row * H + c2]);
        sQ[row * AP + c2] = v.x; sQ[row * AP + c2 + 1] = v.y;
    }
    __syncthreads();

    float m_prev[4], lsum[4], acc[4][8];
#pragma unroll
    for (int i = 0; i < 4; i++) {
        m_prev[i] = -1e30f; lsum[i] = 0.f;
#pragma unroll
        for (int m = 0; m < 8; m++) acc[i][m] = 0.f;
    }

    const int ntiles = (vcnt + 63) >> 6;
    for (int kt = 0; kt < ntiles; kt++) {
        const int base = kt << 6;
        const int nval = min(64, vcnt - base);

        // gather K/V tiles (row-coalesced)
#pragma unroll
        for (int it = 0; it < 16; it++) {
            int e = tid + it * 128;
            int row = e >> 5, c2 = (e & 31) << 1;
            int grow = sIdx[base + ((row < nval) ? row : 0)];
            float2 kv = *reinterpret_cast<const float2*>(&Kb[(size_t)grow * H + c2]);
            float2 vv = *reinterpret_cast<const float2*>(&Vb[(size_t)grow * H + c2]);
            sKP[row * AP + c2] = kv.x; sKP[row * AP + c2 + 1] = kv.y;
            sV [row * AP + c2] = vv.x; sV [row * AP + c2 + 1] = vv.y;
        }
        __syncthreads();

        // scores: rows r_i = ty*4+i, cols c_j = tx+8j
        float s[4][8];
#pragma unroll
        for (int i = 0; i < 4; i++)
#pragma unroll
            for (int j = 0; j < 8; j++) s[i][j] = 0.f;

#pragma unroll 4
        for (int d2 = 0; d2 < HD_; d2 += 2) {
            float2 q2[4], k2[8];
#pragma unroll
            for (int i = 0; i < 4; i++)
                q2[i] = *reinterpret_cast<const float2*>(&sQ[(ty * 4 + i) * AP + d2]);
#pragma unroll
            for (int j = 0; j < 8; j++)
                k2[j] = *reinterpret_cast<const float2*>(&sKP[(tx + 8 * j) * AP + d2]);
#pragma unroll
            for (int i = 0; i < 4; i++)
#pragma unroll
                for (int j = 0; j < 8; j++) {
                    s[i][j] = fmaf(q2[i].x, k2[j].x, s[i][j]);
                    s[i][j] = fmaf(q2[i].y, k2[j].y, s[i][j]);
                }
        }
#pragma unroll
        for (int i = 0; i < 4; i++)
#pragma unroll
            for (int j = 0; j < 8; j++)
                s[i][j] = (tx + 8 * j < nval) ? s[i][j] * 0.125f : -1e9f;

        // online softmax update (per row, replicated over tx)
#pragma unroll
        for (int i = 0; i < 4; i++) {
            float mt = s[i][0];
#pragma unroll
            for (int j = 1; j < 8; j++) mt = fmaxf(mt, s[i][j]);
            mt = fmaxf(mt, __shfl_xor_sync(0xffffffffu, mt, 1));
            mt = fmaxf(mt, __shfl_xor_sync(0xffffffffu, mt, 2));
            mt = fmaxf(mt, __shfl_xor_sync(0xffffffffu, mt, 4));
            float m_new = fmaxf(m_prev[i], mt);
            float corr = exp2p((m_prev[i] - m_new) * LOG2E);
            m_prev[i] = m_new;
            lsum[i] *= corr;
#pragma unroll
            for (int m = 0; m < 8; m++) acc[i][m] *= corr;
            float psum = 0.f;
#pragma unroll
            for (int j = 0; j < 8; j++) {
                float p = exp2p((s[i][j] - m_new) * LOG2E);
                psum += p;
                s[i][j] = p;
            }
            psum += __shfl_xor_sync(0xffffffffu, psum, 1);
            psum += __shfl_xor_sync(0xffffffffu, psum, 2);
            psum += __shfl_xor_sync(0xffffffffu, psum, 4);
            lsum[i] += psum;
        }
        __syncthreads();   // everyone done reading sKP as K

        // store P transposed: sP[key][row]
#pragma unroll
        for (int j = 0; j < 8; j++)
#pragma unroll
            for (int i = 0; i < 4; i++)
                sKP[(tx + 8 * j) * AP + ty * 4 + i] = s[i][j];
        __syncthreads();

        // O += P^T-gather * V : rows r_i, dcols tx*8 + 0..7
#pragma unroll 2
        for (int j = 0; j < 64; j++) {
            float2 p01 = *reinterpret_cast<const float2*>(&sKP[j * AP + ty * 4]);
            float2 p23 = *reinterpret_cast<const float2*>(&sKP[j * AP + ty * 4 + 2]);
            float pr[4] = { p01.x, p01.y, p23.x, p23.y };
            float2 v2[4];
#pragma unroll
            for (int m = 0; m < 4; m++)
                v2[m] = *reinterpret_cast<const float2*>(&sV[j * AP + tx * 8 + 2 * m]);
#pragma unroll
            for (int i = 0; i < 4; i++)
#pragma unroll
                for (int m = 0; m < 4; m++) {
                    acc[i][2 * m]     = fmaf(pr[i], v2[m].x, acc[i][2 * m]);
                    acc[i][2 * m + 1] = fmaf(pr[i], v2[m].y, acc[i][2 * m + 1]);
                }
        }
        __syncthreads();   // before next tile overwrites sKP/sV
    }

    float* Ob = O + (size_t)(b * T_ + qt * 64) * H + nh * HD_;
#pragma unroll
    for (int i = 0; i < 4; i++) {
        float inv = 1.0f / lsum[i];
        float* orow = Ob + (ty * 4 + i) * H + tx * 8;
#pragma unroll
        for (int m = 0; m < 4; m++) {
            float2 o;
            o.x = rna_tf32(acc[i][2 * m] * inv);       // pre-rounded for O-proj GEMM
            o.y = rna_tf32(acc[i][2 * m + 1] * inv);
            *reinterpret_cast<float2*>(&orow[2 * m]) = o;
        }
    }
}

// ============================================================
// launch
// ============================================================
extern "C" void kernel_launch(void* const* d_in, const int* in_sizes, int n_in,
                              void* d_out, int out_size) {
    (void)in_sizes; (void)n_in; (void)out_size;
    const float* x  = (const float*)d_in[0];
    const int*  mask = (const int*) d_in[1];
    const float* Wq = (const float*)d_in[2];
    const float* bq = (const float*)d_in[3];
    const float* Aq = (const float*)d_in[4];
    const float* Bq = (const float*)d_in[5];
    const float* Wk = (const float*)d_in[6];
    const float* bk = (const float*)d_in[7];
    const float* Wv = (const float*)d_in[8];
    const float* bv = (const float*)d_in[9];
    const float* Av = (const float*)d_in[10];
    const float* Bv = (const float*)d_in[11];
    const float* Wo = (const float*)d_in[12];
    const float* bo = (const float*)d_in[13];
    float* out = (float*)d_out;

    float *pxt, *pweff_q, *pweff_v, *pwkt, *pwot, *pq, *pk, *pv, *pao;
    cudaGetSymbolAddress((void**)&pxt, g_xt);
    cudaGetSymbolAddress((void**)&pweff_q, g_weff_q);
    cudaGetSymbolAddress((void**)&pweff_v, g_weff_v);
    cudaGetSymbolAddress((void**)&pwkt, g_wkt);
    cudaGetSymbolAddress((void**)&pwot, g_wot);
    cudaGetSymbolAddress((void**)&pq, g_q);
    cudaGetSymbolAddress((void**)&pk, g_k);
    cudaGetSymbolAddress((void**)&pv, g_v);
    cudaGetSymbolAddress((void**)&pao, g_ao);

    static bool attr_set = false;
    if (!attr_set) {
        cudaFuncSetAttribute(attn_kernel,
            cudaFuncAttributeMaxDynamicSharedMemorySize, (3 * 64 * AP + T_) * 4);
        attr_set = true;
    }

    // prep: round operands to tf32, fold LoRA, compact mask
    cvt_rna_kernel<<<(NROWS * H + 255) / 256, 256>>>(x, pxt, NROWS * H);
    cvt_rna_kernel<<<(H * H + 255) / 256, 256>>>(Wk, pwkt, H * H);
    cvt_rna_kernel<<<(H * H + 255) / 256, 256>>>(Wo, pwot, H * H);
    weff_kernel<1><<<(H * H + 255) / 256, 256>>>(Wq, Aq, Bq);
    weff_kernel<2><<<(H * H + 255) / 256, 256>>>(Wv, Av, Bv);
    compact_kernel<<<B_, 32>>>(mask);

    // fused Q/K/V projection
    gemm_mma<<<dim3(18, NROWS / 128), 256>>>(
        pxt, pweff_q, pwkt, pweff_v, bq, bk, bv, pq, pk, pv);

    // attention
    attn_kernel<<<dim3(T_ / 64, NH_, B_), 128, (3 * 64 * AP + T_) * 4>>>(
        pq, pk, pv, pao);

    // output projection
    gemm_mma<<<dim3(6, NROWS / 128), 256>>>(
        pao, pwot, pwot, pwot, bo, bo, bo, out, out, out);
}